// round 14
// baseline (speedup 1.0000x reference)
#include <cuda_runtime.h>
#include <cuda_bf16.h>
#include <cstdint>

#define N_NODES 100000
#define E_EDGES 1600000
#define D 64
#define EPA 72       // bf16 row pitch for K=64 tiles (144 B)
#define EPN 136      // bf16 row pitch for K=128 tiles (272 B)
#define NTILES (E_EDGES / 128)   // 12500
#define EGRID 296                // persistent edge CTAs (2 per SM)

// Scratch (device globals — no dynamic allocation allowed)
__device__ float g_acc[2 * N_NODES * D];   // [v-sums | u-sums]
__device__ float g_deg[2 * N_NODES];       // [deg_v | deg_u]
__device__ float g_hweb[N_NODES * D];      // h @ We_h^T + be

extern __shared__ char smem_raw[];

// ---------------------------------------------------------------------------
// shared helpers
// ---------------------------------------------------------------------------
__device__ __forceinline__ void mma_bf16(float c[4], const unsigned a[4], const unsigned b[2]) {
    asm volatile(
        "mma.sync.aligned.m16n8k16.row.col.f32.bf16.bf16.f32 "
        "{%0,%1,%2,%3}, {%4,%5,%6,%7}, {%8,%9}, {%0,%1,%2,%3};"
        : "+f"(c[0]), "+f"(c[1]), "+f"(c[2]), "+f"(c[3])
        : "r"(a[0]), "r"(a[1]), "r"(a[2]), "r"(a[3]), "r"(b[0]), "r"(b[1]));
}
__device__ __forceinline__ void ldsm_x4(unsigned r[4], uint32_t addr) {
    asm volatile("ldmatrix.sync.aligned.m8n8.x4.shared.b16 {%0,%1,%2,%3}, [%4];"
                 : "=r"(r[0]), "=r"(r[1]), "=r"(r[2]), "=r"(r[3]) : "r"(addr));
}
__device__ __forceinline__ void ldsm_x2(unsigned r[2], uint32_t addr) {
    asm volatile("ldmatrix.sync.aligned.m8n8.x2.shared.b16 {%0,%1}, [%2];"
                 : "=r"(r[0]), "=r"(r[1]) : "r"(addr));
}
// Fast truncation split: hi = top-16-bits bf16 pair (1 PRMT), lo = rn(x - hi)
// packed by one cvt.bf16x2. 6 ops/pair. Residual x-hi is exact in fp32.
__device__ __forceinline__ void split2(float x, float y, unsigned& hi, unsigned& lo) {
    unsigned xi = __float_as_uint(x), yi = __float_as_uint(y);
    asm("prmt.b32 %0, %1, %2, 0x7632;" : "=r"(hi) : "r"(xi), "r"(yi));
    float xh = __uint_as_float(xi & 0xFFFF0000u);
    float yh = __uint_as_float(yi & 0xFFFF0000u);
    float xl = x - xh, yl = y - yh;
    asm("cvt.rn.satfinite.bf16x2.f32 %0, %1, %2;" : "=r"(lo) : "f"(yl), "f"(xl));
}
static __device__ __forceinline__ uint32_t smem_u32e(const void* p) {
    uint32_t a;
    asm("{ .reg .u64 t; cvta.to.shared.u64 t, %1; cvt.u32.u64 %0, t; }" : "=r"(a) : "l"(p));
    return a;
}
__device__ __forceinline__ float4 ldg_cs4(const float4* p) { return __ldcs(p); }
__device__ __forceinline__ void stg_cs2(float* p, float x, float y) {
    __stcs((float2*)p, make_float2(x, y));
}

// ---------------------------------------------------------------------------
// Stage 1: scatter-add (L2-atomic-bound at its floor — frozen)
// ---------------------------------------------------------------------------
__device__ __forceinline__ void red_add_v4(float* p, float4 f) {
    asm volatile("red.global.add.v4.f32 [%0], {%1,%2,%3,%4};"
                 :: "l"(p), "f"(f.x), "f"(f.y), "f"(f.z), "f"(f.w) : "memory");
}

__global__ void scatter_kernel(const float4* __restrict__ ef4,
                               const int* __restrict__ u,
                               const int* __restrict__ v) {
    int idx = blockIdx.x * blockDim.x + threadIdx.x;  // exactly E*16
    int e = idx >> 4;
    int c = idx & 15;
    float4 f = ldg_cs4(ef4 + idx);
    int vv = v[e];
    int uu = u[e];
    red_add_v4(&g_acc[(vv << 6) + (c << 2)], f);
    red_add_v4(&g_acc[(N_NODES << 6) + (uu << 6) + (c << 2)], f);
    if (c == 0) {
        atomicAdd(&g_deg[vv], 1.0f);
        atomicAdd(&g_deg[N_NODES + uu], 1.0f);
    }
}

// ---------------------------------------------------------------------------
// Stage 2 (mma): per-node — means, h = relu(cat @ Wn^T + bn), hweb = h@We_h^T+be
// ---------------------------------------------------------------------------
#define N_A1HI 0
#define N_A1LO (128 * EPN)
#define N_B1HI (2 * 128 * EPN)
#define N_B1LO (2 * 128 * EPN + 64 * EPN)
#define N_ELEMS (2 * 128 * EPN + 2 * 64 * EPN)
#define N_SMEM_BYTES (N_ELEMS * 2)          // 104448
#define N_A2HI 0
#define N_A2LO (128 * EPA)
#define N_B2HI (2 * 128 * EPA)
#define N_B2LO (2 * 128 * EPA + 64 * EPA)

__global__ void __launch_bounds__(256, 2)
node_kernel(const float* __restrict__ Wn,
            const float* __restrict__ bn,
            const float* __restrict__ We,
            const float* __restrict__ be,
            float* __restrict__ h_out) {
    __nv_bfloat16* bs = (__nv_bfloat16*)smem_raw;
    int t = threadIdx.x;
    int nb = blockIdx.x * 128;

    {
        int row = t >> 1, half = t & 1;
        int n = nb + row;
        bool ok = (n < N_NODES);
        float s = 0.f;
        const float4* src = (const float4*)g_acc;
        if (half == 0) { if (ok) s = 1.0f / fmaxf(g_deg[n], 1.0f); src += (size_t)n * 16; }
        else           { if (ok) s = 1.0f / fmaxf(g_deg[N_NODES + n], 1.0f); src += (size_t)(N_NODES + n) * 16; }
        unsigned* dh = (unsigned*)&bs[N_A1HI + row * EPN + half * 64];
        unsigned* dl = (unsigned*)&bs[N_A1LO + row * EPN + half * 64];
#pragma unroll
        for (int i = 0; i < 16; i++) {
            float4 f = ok ? src[i] : make_float4(0.f, 0.f, 0.f, 0.f);
            f.x *= s; f.y *= s; f.z *= s; f.w *= s;
            unsigned h0, l0, h1, l1;
            split2(f.x, f.y, h0, l0);
            split2(f.z, f.w, h1, l1);
            dh[i * 2 + 0] = h0; dh[i * 2 + 1] = h1;
            dl[i * 2 + 0] = l0; dl[i * 2 + 1] = l1;
        }
    }
    {
        int o = t >> 2, q = t & 3;
        const float4* src = (const float4*)Wn + o * 32 + q * 8;
        unsigned* dh = (unsigned*)&bs[N_B1HI + o * EPN + q * 32];
        unsigned* dl = (unsigned*)&bs[N_B1LO + o * EPN + q * 32];
#pragma unroll
        for (int i = 0; i < 8; i++) {
            float4 f = src[i];
            unsigned h0, l0, h1, l1;
            split2(f.x, f.y, h0, l0);
            split2(f.z, f.w, h1, l1);
            dh[i * 2 + 0] = h0; dh[i * 2 + 1] = h1;
            dl[i * 2 + 0] = l0; dl[i * 2 + 1] = l1;
        }
    }
    __syncthreads();

    int wid = t >> 5, lane = t & 31;
    int wm = wid & 3, wn = wid >> 2;
    int g = lane >> 2, tg = lane & 3;

    int a_row_off = lane & 15;
    int a_col_off = (lane >> 4) << 3;
    int b_lane = lane & 15;
    int b_row_off = (b_lane < 8) ? b_lane : (b_lane - 8);
    int b_col_off = (b_lane < 8) ? 0 : 8;

    float c[2][4][4] = {};
    {
        uint32_t ahi = smem_u32e(&bs[N_A1HI + (wm * 32 + a_row_off) * EPN + a_col_off]);
        uint32_t alo = smem_u32e(&bs[N_A1LO + (wm * 32 + a_row_off) * EPN + a_col_off]);
        uint32_t bhi = smem_u32e(&bs[N_B1HI + (wn * 32 + b_row_off) * EPN + b_col_off]);
        uint32_t blo = smem_u32e(&bs[N_B1LO + (wn * 32 + b_row_off) * EPN + b_col_off]);
#pragma unroll
        for (int ks = 0; ks < 8; ks++) {
            uint32_t kb = ks * 32;
            unsigned ah[2][4], al[2][4];
            ldsm_x4(ah[0], ahi + kb);
            ldsm_x4(ah[1], ahi + kb + 16 * EPN * 2);
            ldsm_x4(al[0], alo + kb);
            ldsm_x4(al[1], alo + kb + 16 * EPN * 2);
            unsigned bh[4][2], bl[4][2];
#pragma unroll
            for (int nt = 0; nt < 4; nt++) {
                ldsm_x2(bh[nt], bhi + kb + nt * 8 * EPN * 2);
                ldsm_x2(bl[nt], blo + kb + nt * 8 * EPN * 2);
            }
#pragma unroll
            for (int mt = 0; mt < 2; mt++)
#pragma unroll
                for (int nt = 0; nt < 4; nt++) {
                    mma_bf16(c[mt][nt], ah[mt], bh[nt]);
                    mma_bf16(c[mt][nt], ah[mt], bl[nt]);
                    mma_bf16(c[mt][nt], al[mt], bh[nt]);
                }
        }
    }
    __syncthreads();

    // epilogue1: relu(+bn), write h (streaming), store A2 split of h
#pragma unroll
    for (int mt = 0; mt < 2; mt++) {
        int r0 = wm * 32 + mt * 16 + g;
        int r1 = r0 + 8;
#pragma unroll
        for (int nt = 0; nt < 4; nt++) {
            int col = wn * 32 + nt * 8 + 2 * tg;
            float2 bnv = *(const float2*)&bn[col];
            float v00 = fmaxf(c[mt][nt][0] + bnv.x, 0.f);
            float v01 = fmaxf(c[mt][nt][1] + bnv.y, 0.f);
            float v10 = fmaxf(c[mt][nt][2] + bnv.x, 0.f);
            float v11 = fmaxf(c[mt][nt][3] + bnv.y, 0.f);
            unsigned h0, l0, h1, l1;
            split2(v00, v01, h0, l0);
            split2(v10, v11, h1, l1);
            *(unsigned*)&bs[N_A2HI + r0 * EPA + col] = h0;
            *(unsigned*)&bs[N_A2LO + r0 * EPA + col] = l0;
            *(unsigned*)&bs[N_A2HI + r1 * EPA + col] = h1;
            *(unsigned*)&bs[N_A2LO + r1 * EPA + col] = l1;
            if (nb + r0 < N_NODES)
                stg_cs2(&h_out[(size_t)(nb + r0) * 64 + col], v00, v01);
            if (nb + r1 < N_NODES)
                stg_cs2(&h_out[(size_t)(nb + r1) * 64 + col], v10, v11);
        }
    }
    {
        int o = t >> 2, q = t & 3;
        const float4* src = (const float4*)We + o * 32 + q * 4;
        unsigned* dh = (unsigned*)&bs[N_B2HI + o * EPA + q * 16];
        unsigned* dl = (unsigned*)&bs[N_B2LO + o * EPA + q * 16];
#pragma unroll
        for (int i = 0; i < 4; i++) {
            float4 f = src[i];
            unsigned h0, l0, h1, l1;
            split2(f.x, f.y, h0, l0);
            split2(f.z, f.w, h1, l1);
            dh[i * 2 + 0] = h0; dh[i * 2 + 1] = h1;
            dl[i * 2 + 0] = l0; dl[i * 2 + 1] = l1;
        }
    }
    __syncthreads();

    float c2[2][4][4] = {};
    {
        uint32_t ahi = smem_u32e(&bs[N_A2HI + (wm * 32 + a_row_off) * EPA + a_col_off]);
        uint32_t alo = smem_u32e(&bs[N_A2LO + (wm * 32 + a_row_off) * EPA + a_col_off]);
        uint32_t bhi = smem_u32e(&bs[N_B2HI + (wn * 32 + b_row_off) * EPA + b_col_off]);
        uint32_t blo = smem_u32e(&bs[N_B2LO + (wn * 32 + b_row_off) * EPA + b_col_off]);
#pragma unroll
        for (int ks = 0; ks < 4; ks++) {
            uint32_t kb = ks * 32;
            unsigned ah[2][4], al[2][4];
            ldsm_x4(ah[0], ahi + kb);
            ldsm_x4(ah[1], ahi + kb + 16 * EPA * 2);
            ldsm_x4(al[0], alo + kb);
            ldsm_x4(al[1], alo + kb + 16 * EPA * 2);
            unsigned bh[4][2], bl[4][2];
#pragma unroll
            for (int nt = 0; nt < 4; nt++) {
                ldsm_x2(bh[nt], bhi + kb + nt * 8 * EPA * 2);
                ldsm_x2(bl[nt], blo + kb + nt * 8 * EPA * 2);
            }
#pragma unroll
            for (int mt = 0; mt < 2; mt++)
#pragma unroll
                for (int nt = 0; nt < 4; nt++) {
                    mma_bf16(c2[mt][nt], ah[mt], bh[nt]);
                    mma_bf16(c2[mt][nt], ah[mt], bl[nt]);
                    mma_bf16(c2[mt][nt], al[mt], bh[nt]);
                }
        }
    }

#pragma unroll
    for (int mt = 0; mt < 2; mt++) {
        int r0 = wm * 32 + mt * 16 + g;
        int r1 = r0 + 8;
#pragma unroll
        for (int nt = 0; nt < 4; nt++) {
            int col = wn * 32 + nt * 8 + 2 * tg;
            float2 bev = *(const float2*)&be[col];
            if (nb + r0 < N_NODES)
                *(float2*)&g_hweb[(size_t)(nb + r0) * 64 + col] =
                    make_float2(c2[mt][nt][0] + bev.x, c2[mt][nt][1] + bev.y);
            if (nb + r1 < N_NODES)
                *(float2*)&g_hweb[(size_t)(nb + r1) * 64 + col] =
                    make_float2(c2[mt][nt][2] + bev.x, c2[mt][nt][3] + bev.y);
        }
    }
}

// ---------------------------------------------------------------------------
// Stage 3: edge = hweb[u[e]] + efeats[e] @ We_e^T   (bf16x3, persistent,
// double-buffered A, ONE sync per tile; convert overlaps mainloop across warps)
// ---------------------------------------------------------------------------
#define ABUF (2 * 128 * EPA)               // elems per A buffer (hi+lo) = 18432
#define ABUF_BYTES (ABUF * 2)              // 36864
#define SM2_BHI (2 * ABUF)                 // after both A buffers
#define SM2_BLO (2 * ABUF + 64 * EPA)
#define SM2_U_OFF (2 * ABUF + 2 * 64 * EPA)   // elem offset; int[2][128] after
#define SM2_EDGE_BYTES (SM2_U_OFF * 2 + 2 * 128 * 4)   // 93184

__global__ void __launch_bounds__(256, 2)
edge_kernel(const float* __restrict__ efeats,
            const int* __restrict__ u,
            const float* __restrict__ We,
            float* __restrict__ edge_out) {
    __nv_bfloat16* bs = (__nv_bfloat16*)smem_raw;
    __nv_bfloat16* B_hi = bs + SM2_BHI;
    __nv_bfloat16* B_lo = bs + SM2_BLO;
    int* u_s = (int*)(bs + SM2_U_OFF);     // [2][128]

    int t = threadIdx.x;
    int row = t >> 1, half = t & 1;

    // ---- B fill ONCE per CTA: We_e = We[:, 64:128]
    {
        int o = t >> 2, q = t & 3;
        const float4* src = (const float4*)We + o * 32 + 16 + q * 4;
        unsigned* dh = (unsigned*)&B_hi[o * EPA + q * 16];
        unsigned* dl = (unsigned*)&B_lo[o * EPA + q * 16];
#pragma unroll
        for (int i = 0; i < 4; i++) {
            float4 f = src[i];
            unsigned h0, l0, h1, l1;
            split2(f.x, f.y, h0, l0);
            split2(f.z, f.w, h1, l1);
            dh[i * 2 + 0] = h0; dh[i * 2 + 1] = h1;
            dl[i * 2 + 0] = l0; dl[i * 2 + 1] = l1;
        }
    }

    int wid = t >> 5, lane = t & 31;
    int wm = wid & 3, wn = wid >> 2;
    int g = lane >> 2, tg = lane & 3;

    int a_row_off = lane & 15;
    int a_col_off = (lane >> 4) << 3;
    uint32_t ahi0 = smem_u32e(&bs[(wm * 32 + a_row_off) * EPA + a_col_off]);
    uint32_t alo0 = ahi0 + 128 * EPA * 2;
    int b_lane = lane & 15;
    int b_row_off = (b_lane < 8) ? b_lane : (b_lane - 8);
    int b_col_off = (b_lane < 8) ? 0 : 8;
    uint32_t bhi_base = smem_u32e(&B_hi[(wn * 32 + b_row_off) * EPA + b_col_off]);
    uint32_t blo_base = smem_u32e(&B_lo[(wn * 32 + b_row_off) * EPA + b_col_off]);

    // convert destination bases (thread-local)
    unsigned* cvt_dh0 = (unsigned*)&bs[row * EPA + half * 32];

    // ---- prefetch + convert first tile into buffer 0
    int tile = blockIdx.x;
    float4 pf[8];
    int pu = 0;
    {
        const float4* src = (const float4*)efeats + ((size_t)tile * 128 + row) * 16 + half * 8;
#pragma unroll
        for (int i = 0; i < 8; i++) pf[i] = ldg_cs4(src + i);
        if (t < 128) pu = u[tile * 128 + t];
    }
    {
        unsigned* dh = cvt_dh0;
        unsigned* dl = (unsigned*)((char*)cvt_dh0 + 128 * EPA * 2);
#pragma unroll
        for (int i = 0; i < 8; i++) {
            unsigned h0, l0, h1, l1;
            split2(pf[i].x, pf[i].y, h0, l0);
            split2(pf[i].z, pf[i].w, h1, l1);
            dh[i * 2 + 0] = h0; dh[i * 2 + 1] = h1;
            dl[i * 2 + 0] = l0; dl[i * 2 + 1] = l1;
        }
        if (t < 128) u_s[t] = pu;
    }
    __syncthreads();   // buffer 0 + B ready

    int buf = 0;
    while (tile < NTILES) {
        int ntile = tile + EGRID;

        // ---- prefetch next tile (latency hides under mainloop+epilogue)
        if (ntile < NTILES) {
            const float4* src = (const float4*)efeats + ((size_t)ntile * 128 + row) * 16 + half * 8;
#pragma unroll
            for (int i = 0; i < 8; i++) pf[i] = ldg_cs4(src + i);
            if (t < 128) pu = u[ntile * 128 + t];
        }

        // ---- mainloop on A[buf]
        uint32_t ahi_base = ahi0 + buf * ABUF_BYTES;
        uint32_t alo_base = alo0 + buf * ABUF_BYTES;
        float c[2][4][4] = {};
#pragma unroll
        for (int ks = 0; ks < 4; ks++) {
            uint32_t kb = ks * 32;
            unsigned ah[2][4], al[2][4];
            ldsm_x4(ah[0], ahi_base + kb);
            ldsm_x4(ah[1], ahi_base + kb + 16 * EPA * 2);
            ldsm_x4(al[0], alo_base + kb);
            ldsm_x4(al[1], alo_base + kb + 16 * EPA * 2);
            unsigned bh[4][2], bl[4][2];
#pragma unroll
            for (int nt = 0; nt < 4; nt++) {
                ldsm_x2(bh[nt], bhi_base + kb + nt * 8 * EPA * 2);
                ldsm_x2(bl[nt], blo_base + kb + nt * 8 * EPA * 2);
            }
#pragma unroll
            for (int mt = 0; mt < 2; mt++)
#pragma unroll
                for (int nt = 0; nt < 4; nt++) {
                    mma_bf16(c[mt][nt], ah[mt], bh[nt]);
                    mma_bf16(c[mt][nt], ah[mt], bl[nt]);
                    mma_bf16(c[mt][nt], al[mt], bh[nt]);
                }
        }

        // ---- epilogue: batch gathers (MLP 16), then add + store
        size_t eb = (size_t)tile * 128;
        const int* ub = u_s + buf * 128;
        float2 gv[2][4][2];
#pragma unroll
        for (int mt = 0; mt < 2; mt++) {
            int r0 = wm * 32 + mt * 16 + g;
            int u0 = ub[r0], u1 = ub[r0 + 8];
#pragma unroll
            for (int nt = 0; nt < 4; nt++) {
                int col = wn * 32 + nt * 8 + 2 * tg;
                gv[mt][nt][0] = *(const float2*)&g_hweb[(size_t)u0 * 64 + col];
                gv[mt][nt][1] = *(const float2*)&g_hweb[(size_t)u1 * 64 + col];
            }
        }
#pragma unroll
        for (int mt = 0; mt < 2; mt++) {
            int r0 = wm * 32 + mt * 16 + g;
            size_t e0 = eb + r0, e1 = eb + r0 + 8;
#pragma unroll
            for (int nt = 0; nt < 4; nt++) {
                int col = wn * 32 + nt * 8 + 2 * tg;
                stg_cs2(&edge_out[e0 * 64 + col],
                        c[mt][nt][0] + gv[mt][nt][0].x, c[mt][nt][1] + gv[mt][nt][0].y);
                stg_cs2(&edge_out[e1 * 64 + col],
                        c[mt][nt][2] + gv[mt][nt][1].x, c[mt][nt][3] + gv[mt][nt][1].y);
            }
        }

        // ---- convert next tile into A[buf^1] (other warps may still be in
        // mainloop(A[buf]) — different buffer, safe)
        if (ntile < NTILES) {
            unsigned* dh = (unsigned*)((char*)cvt_dh0 + (buf ^ 1) * ABUF_BYTES);
            unsigned* dl = (unsigned*)((char*)dh + 128 * EPA * 2);
#pragma unroll
            for (int i = 0; i < 8; i++) {
                unsigned h0, l0, h1, l1;
                split2(pf[i].x, pf[i].y, h0, l0);
                split2(pf[i].z, pf[i].w, h1, l1);
                dh[i * 2 + 0] = h0; dh[i * 2 + 1] = h1;
                dl[i * 2 + 0] = l0; dl[i * 2 + 1] = l1;
            }
            if (t < 128) u_s[(buf ^ 1) * 128 + t] = pu;
        }
        __syncthreads();   // next buffer ready; everyone done with A[buf]

        buf ^= 1;
        tile = ntile;
    }
}

// ---------------------------------------------------------------------------
extern "C" void kernel_launch(void* const* d_in, const int* in_sizes, int n_in,
                              void* d_out, int out_size) {
    // inputs: [0]=nfeats (unused), [1]=efeats, [2]=u, [3]=v, [4]=Wn, [5]=bn, [6]=We, [7]=be
    const float* efeats = (const float*)d_in[1];
    const int*   u      = (const int*)d_in[2];
    const int*   v      = (const int*)d_in[3];
    const float* Wn     = (const float*)d_in[4];
    const float* bn     = (const float*)d_in[5];
    const float* We     = (const float*)d_in[6];
    const float* be     = (const float*)d_in[7];

    float* out      = (float*)d_out;
    float* h_out    = out;                               // [N,64]
    float* edge_out = out + (size_t)N_NODES * 64;        // [E,64]

    void* accp = nullptr; cudaGetSymbolAddress(&accp, g_acc);
    void* degp = nullptr; cudaGetSymbolAddress(&degp, g_deg);
    cudaMemsetAsync(accp, 0, sizeof(float) * 2 * N_NODES * D, 0);
    cudaMemsetAsync(degp, 0, sizeof(float) * 2 * N_NODES, 0);

    scatter_kernel<<<(E_EDGES * 16) / 256, 256>>>((const float4*)efeats, u, v);

    cudaFuncSetAttribute(node_kernel, cudaFuncAttributeMaxDynamicSharedMemorySize, N_SMEM_BYTES);
    node_kernel<<<(N_NODES + 127) / 128, 256, N_SMEM_BYTES>>>(Wn, bn, We, be, h_out);

    cudaFuncSetAttribute(edge_kernel, cudaFuncAttributeMaxDynamicSharedMemorySize, SM2_EDGE_BYTES);
    edge_kernel<<<EGRID, 256, SM2_EDGE_BYTES>>>(efeats, u, We, edge_out);
}

// round 15
// speedup vs baseline: 1.0337x; 1.0337x over previous
#include <cuda_runtime.h>
#include <cuda_bf16.h>
#include <cstdint>

#define N_NODES 100000
#define E_EDGES 1600000
#define D 64
#define EPA 72       // bf16 row pitch for K=64 tiles (144 B)
#define EPN 136      // bf16 row pitch for K=128 tiles (272 B)
#define NTILES (E_EDGES / 128)   // 12500
#define EGRID 296                // persistent edge CTAs (2 per SM)

// Scratch (device globals — no dynamic allocation allowed)
__device__ float g_acc[2 * N_NODES * D];   // [v-sums | u-sums]
__device__ float g_deg[2 * N_NODES];       // [deg_v | deg_u]
__device__ float g_hweb[N_NODES * D];      // h @ We_h^T + be

extern __shared__ char smem_raw[];

// ---------------------------------------------------------------------------
// shared helpers
// ---------------------------------------------------------------------------
__device__ __forceinline__ void mma_bf16(float c[4], const unsigned a[4], const unsigned b[2]) {
    asm volatile(
        "mma.sync.aligned.m16n8k16.row.col.f32.bf16.bf16.f32 "
        "{%0,%1,%2,%3}, {%4,%5,%6,%7}, {%8,%9}, {%0,%1,%2,%3};"
        : "+f"(c[0]), "+f"(c[1]), "+f"(c[2]), "+f"(c[3])
        : "r"(a[0]), "r"(a[1]), "r"(a[2]), "r"(a[3]), "r"(b[0]), "r"(b[1]));
}
__device__ __forceinline__ void ldsm_x4(unsigned r[4], uint32_t addr) {
    asm volatile("ldmatrix.sync.aligned.m8n8.x4.shared.b16 {%0,%1,%2,%3}, [%4];"
                 : "=r"(r[0]), "=r"(r[1]), "=r"(r[2]), "=r"(r[3]) : "r"(addr));
}
__device__ __forceinline__ void ldsm_x2(unsigned r[2], uint32_t addr) {
    asm volatile("ldmatrix.sync.aligned.m8n8.x2.shared.b16 {%0,%1}, [%2];"
                 : "=r"(r[0]), "=r"(r[1]) : "r"(addr));
}
// Fast truncation split: hi = top-16-bits bf16 pair (1 PRMT), lo = rn(x - hi)
// packed by one cvt.bf16x2. Residual x-hi is exact in fp32.
__device__ __forceinline__ void split2(float x, float y, unsigned& hi, unsigned& lo) {
    unsigned xi = __float_as_uint(x), yi = __float_as_uint(y);
    asm("prmt.b32 %0, %1, %2, 0x7632;" : "=r"(hi) : "r"(xi), "r"(yi));
    float xh = __uint_as_float(xi & 0xFFFF0000u);
    float yh = __uint_as_float(yi & 0xFFFF0000u);
    float xl = x - xh, yl = y - yh;
    asm("cvt.rn.satfinite.bf16x2.f32 %0, %1, %2;" : "=r"(lo) : "f"(yl), "f"(xl));
}
static __device__ __forceinline__ uint32_t smem_u32e(const void* p) {
    uint32_t a;
    asm("{ .reg .u64 t; cvta.to.shared.u64 t, %1; cvt.u32.u64 %0, t; }" : "=r"(a) : "l"(p));
    return a;
}
__device__ __forceinline__ float4 ldg_cs4(const float4* p) { return __ldcs(p); }
__device__ __forceinline__ void stg_cs2(float* p, float x, float y) {
    __stcs((float2*)p, make_float2(x, y));
}

// ---------------------------------------------------------------------------
// Stage 1: scatter-add (L2-atomic-bound at its floor — frozen)
// ---------------------------------------------------------------------------
__device__ __forceinline__ void red_add_v4(float* p, float4 f) {
    asm volatile("red.global.add.v4.f32 [%0], {%1,%2,%3,%4};"
                 :: "l"(p), "f"(f.x), "f"(f.y), "f"(f.z), "f"(f.w) : "memory");
}

__global__ void scatter_kernel(const float4* __restrict__ ef4,
                               const int* __restrict__ u,
                               const int* __restrict__ v) {
    int idx = blockIdx.x * blockDim.x + threadIdx.x;  // exactly E*16
    int e = idx >> 4;
    int c = idx & 15;
    float4 f = ldg_cs4(ef4 + idx);
    int vv = v[e];
    int uu = u[e];
    red_add_v4(&g_acc[(vv << 6) + (c << 2)], f);
    red_add_v4(&g_acc[(N_NODES << 6) + (uu << 6) + (c << 2)], f);
    if (c == 0) {
        atomicAdd(&g_deg[vv], 1.0f);
        atomicAdd(&g_deg[N_NODES + uu], 1.0f);
    }
}

// ---------------------------------------------------------------------------
// Stage 2 (mma): per-node — means, h = relu(cat @ Wn^T + bn), hweb = h@We_h^T+be
// ---------------------------------------------------------------------------
#define N_A1HI 0
#define N_A1LO (128 * EPN)
#define N_B1HI (2 * 128 * EPN)
#define N_B1LO (2 * 128 * EPN + 64 * EPN)
#define N_ELEMS (2 * 128 * EPN + 2 * 64 * EPN)
#define N_SMEM_BYTES (N_ELEMS * 2)          // 104448
#define N_A2HI 0
#define N_A2LO (128 * EPA)
#define N_B2HI (2 * 128 * EPA)
#define N_B2LO (2 * 128 * EPA + 64 * EPA)

__global__ void __launch_bounds__(256, 2)
node_kernel(const float* __restrict__ Wn,
            const float* __restrict__ bn,
            const float* __restrict__ We,
            const float* __restrict__ be,
            float* __restrict__ h_out) {
    __nv_bfloat16* bs = (__nv_bfloat16*)smem_raw;
    int t = threadIdx.x;
    int nb = blockIdx.x * 128;

    {
        int row = t >> 1, half = t & 1;
        int n = nb + row;
        bool ok = (n < N_NODES);
        float s = 0.f;
        const float4* src = (const float4*)g_acc;
        if (half == 0) { if (ok) s = 1.0f / fmaxf(g_deg[n], 1.0f); src += (size_t)n * 16; }
        else           { if (ok) s = 1.0f / fmaxf(g_deg[N_NODES + n], 1.0f); src += (size_t)(N_NODES + n) * 16; }
        unsigned* dh = (unsigned*)&bs[N_A1HI + row * EPN + half * 64];
        unsigned* dl = (unsigned*)&bs[N_A1LO + row * EPN + half * 64];
#pragma unroll
        for (int i = 0; i < 16; i++) {
            float4 f = ok ? src[i] : make_float4(0.f, 0.f, 0.f, 0.f);
            f.x *= s; f.y *= s; f.z *= s; f.w *= s;
            unsigned h0, l0, h1, l1;
            split2(f.x, f.y, h0, l0);
            split2(f.z, f.w, h1, l1);
            dh[i * 2 + 0] = h0; dh[i * 2 + 1] = h1;
            dl[i * 2 + 0] = l0; dl[i * 2 + 1] = l1;
        }
    }
    {
        int o = t >> 2, q = t & 3;
        const float4* src = (const float4*)Wn + o * 32 + q * 8;
        unsigned* dh = (unsigned*)&bs[N_B1HI + o * EPN + q * 32];
        unsigned* dl = (unsigned*)&bs[N_B1LO + o * EPN + q * 32];
#pragma unroll
        for (int i = 0; i < 8; i++) {
            float4 f = src[i];
            unsigned h0, l0, h1, l1;
            split2(f.x, f.y, h0, l0);
            split2(f.z, f.w, h1, l1);
            dh[i * 2 + 0] = h0; dh[i * 2 + 1] = h1;
            dl[i * 2 + 0] = l0; dl[i * 2 + 1] = l1;
        }
    }
    __syncthreads();

    int wid = t >> 5, lane = t & 31;
    int wm = wid & 3, wn = wid >> 2;
    int g = lane >> 2, tg = lane & 3;

    int a_row_off = lane & 15;
    int a_col_off = (lane >> 4) << 3;
    int b_lane = lane & 15;
    int b_row_off = (b_lane < 8) ? b_lane : (b_lane - 8);
    int b_col_off = (b_lane < 8) ? 0 : 8;

    float c[2][4][4] = {};
    {
        uint32_t ahi = smem_u32e(&bs[N_A1HI + (wm * 32 + a_row_off) * EPN + a_col_off]);
        uint32_t alo = smem_u32e(&bs[N_A1LO + (wm * 32 + a_row_off) * EPN + a_col_off]);
        uint32_t bhi = smem_u32e(&bs[N_B1HI + (wn * 32 + b_row_off) * EPN + b_col_off]);
        uint32_t blo = smem_u32e(&bs[N_B1LO + (wn * 32 + b_row_off) * EPN + b_col_off]);
#pragma unroll
        for (int ks = 0; ks < 8; ks++) {
            uint32_t kb = ks * 32;
            unsigned ah[2][4], al[2][4];
            ldsm_x4(ah[0], ahi + kb);
            ldsm_x4(ah[1], ahi + kb + 16 * EPN * 2);
            ldsm_x4(al[0], alo + kb);
            ldsm_x4(al[1], alo + kb + 16 * EPN * 2);
            unsigned bh[4][2], bl[4][2];
#pragma unroll
            for (int nt = 0; nt < 4; nt++) {
                ldsm_x2(bh[nt], bhi + kb + nt * 8 * EPN * 2);
                ldsm_x2(bl[nt], blo + kb + nt * 8 * EPN * 2);
            }
#pragma unroll
            for (int mt = 0; mt < 2; mt++)
#pragma unroll
                for (int nt = 0; nt < 4; nt++) {
                    mma_bf16(c[mt][nt], ah[mt], bh[nt]);
                    mma_bf16(c[mt][nt], ah[mt], bl[nt]);
                    mma_bf16(c[mt][nt], al[mt], bh[nt]);
                }
        }
    }
    __syncthreads();

    // epilogue1: relu(+bn), write h (streaming), store A2 split of h
#pragma unroll
    for (int mt = 0; mt < 2; mt++) {
        int r0 = wm * 32 + mt * 16 + g;
        int r1 = r0 + 8;
#pragma unroll
        for (int nt = 0; nt < 4; nt++) {
            int col = wn * 32 + nt * 8 + 2 * tg;
            float2 bnv = *(const float2*)&bn[col];
            float v00 = fmaxf(c[mt][nt][0] + bnv.x, 0.f);
            float v01 = fmaxf(c[mt][nt][1] + bnv.y, 0.f);
            float v10 = fmaxf(c[mt][nt][2] + bnv.x, 0.f);
            float v11 = fmaxf(c[mt][nt][3] + bnv.y, 0.f);
            unsigned h0, l0, h1, l1;
            split2(v00, v01, h0, l0);
            split2(v10, v11, h1, l1);
            *(unsigned*)&bs[N_A2HI + r0 * EPA + col] = h0;
            *(unsigned*)&bs[N_A2LO + r0 * EPA + col] = l0;
            *(unsigned*)&bs[N_A2HI + r1 * EPA + col] = h1;
            *(unsigned*)&bs[N_A2LO + r1 * EPA + col] = l1;
            if (nb + r0 < N_NODES)
                stg_cs2(&h_out[(size_t)(nb + r0) * 64 + col], v00, v01);
            if (nb + r1 < N_NODES)
                stg_cs2(&h_out[(size_t)(nb + r1) * 64 + col], v10, v11);
        }
    }
    {
        int o = t >> 2, q = t & 3;
        const float4* src = (const float4*)We + o * 32 + q * 4;
        unsigned* dh = (unsigned*)&bs[N_B2HI + o * EPA + q * 16];
        unsigned* dl = (unsigned*)&bs[N_B2LO + o * EPA + q * 16];
#pragma unroll
        for (int i = 0; i < 4; i++) {
            float4 f = src[i];
            unsigned h0, l0, h1, l1;
            split2(f.x, f.y, h0, l0);
            split2(f.z, f.w, h1, l1);
            dh[i * 2 + 0] = h0; dh[i * 2 + 1] = h1;
            dl[i * 2 + 0] = l0; dl[i * 2 + 1] = l1;
        }
    }
    __syncthreads();

    float c2[2][4][4] = {};
    {
        uint32_t ahi = smem_u32e(&bs[N_A2HI + (wm * 32 + a_row_off) * EPA + a_col_off]);
        uint32_t alo = smem_u32e(&bs[N_A2LO + (wm * 32 + a_row_off) * EPA + a_col_off]);
        uint32_t bhi = smem_u32e(&bs[N_B2HI + (wn * 32 + b_row_off) * EPA + b_col_off]);
        uint32_t blo = smem_u32e(&bs[N_B2LO + (wn * 32 + b_row_off) * EPA + b_col_off]);
#pragma unroll
        for (int ks = 0; ks < 4; ks++) {
            uint32_t kb = ks * 32;
            unsigned ah[2][4], al[2][4];
            ldsm_x4(ah[0], ahi + kb);
            ldsm_x4(ah[1], ahi + kb + 16 * EPA * 2);
            ldsm_x4(al[0], alo + kb);
            ldsm_x4(al[1], alo + kb + 16 * EPA * 2);
            unsigned bh[4][2], bl[4][2];
#pragma unroll
            for (int nt = 0; nt < 4; nt++) {
                ldsm_x2(bh[nt], bhi + kb + nt * 8 * EPA * 2);
                ldsm_x2(bl[nt], blo + kb + nt * 8 * EPA * 2);
            }
#pragma unroll
            for (int mt = 0; mt < 2; mt++)
#pragma unroll
                for (int nt = 0; nt < 4; nt++) {
                    mma_bf16(c2[mt][nt], ah[mt], bh[nt]);
                    mma_bf16(c2[mt][nt], ah[mt], bl[nt]);
                    mma_bf16(c2[mt][nt], al[mt], bh[nt]);
                }
        }
    }

#pragma unroll
    for (int mt = 0; mt < 2; mt++) {
        int r0 = wm * 32 + mt * 16 + g;
        int r1 = r0 + 8;
#pragma unroll
        for (int nt = 0; nt < 4; nt++) {
            int col = wn * 32 + nt * 8 + 2 * tg;
            float2 bev = *(const float2*)&be[col];
            if (nb + r0 < N_NODES)
                *(float2*)&g_hweb[(size_t)(nb + r0) * 64 + col] =
                    make_float2(c2[mt][nt][0] + bev.x, c2[mt][nt][1] + bev.y);
            if (nb + r1 < N_NODES)
                *(float2*)&g_hweb[(size_t)(nb + r1) * 64 + col] =
                    make_float2(c2[mt][nt][2] + bev.x, c2[mt][nt][3] + bev.y);
        }
    }
}

// ---------------------------------------------------------------------------
// Stage 3: edge = hweb[u[e]] + efeats[e] @ We_e^T   (bf16x3, persistent CTAs,
// R13 structure: single A buffer, 2 syncs/tile, register prefetch; split2 only)
// ---------------------------------------------------------------------------
#define SM_AHI 0
#define SM_ALO (128 * EPA)
#define SM_BHI (2 * 128 * EPA)
#define SM_BLO (2 * 128 * EPA + 64 * EPA)
#define SM_U_OFF (2 * 128 * EPA + 2 * 64 * EPA)
#define SM_EDGE_BYTES (SM_U_OFF * 2 + 128 * 4)

__global__ void __launch_bounds__(256, 2)
edge_kernel(const float* __restrict__ efeats,
            const int* __restrict__ u,
            const float* __restrict__ We,
            float* __restrict__ edge_out) {
    __nv_bfloat16* bs = (__nv_bfloat16*)smem_raw;
    __nv_bfloat16* A_hi = bs + SM_AHI;
    __nv_bfloat16* A_lo = bs + SM_ALO;
    __nv_bfloat16* B_hi = bs + SM_BHI;
    __nv_bfloat16* B_lo = bs + SM_BLO;
    int* u_s = (int*)(bs + SM_U_OFF);

    int t = threadIdx.x;
    int row = t >> 1, half = t & 1;

    // ---- B fill ONCE per CTA: We_e = We[:, 64:128]
    {
        int o = t >> 2, q = t & 3;
        const float4* src = (const float4*)We + o * 32 + 16 + q * 4;
        unsigned* dh = (unsigned*)&B_hi[o * EPA + q * 16];
        unsigned* dl = (unsigned*)&B_lo[o * EPA + q * 16];
#pragma unroll
        for (int i = 0; i < 4; i++) {
            float4 f = src[i];
            unsigned h0, l0, h1, l1;
            split2(f.x, f.y, h0, l0);
            split2(f.z, f.w, h1, l1);
            dh[i * 2 + 0] = h0; dh[i * 2 + 1] = h1;
            dl[i * 2 + 0] = l0; dl[i * 2 + 1] = l1;
        }
    }

    int wid = t >> 5, lane = t & 31;
    int wm = wid & 3, wn = wid >> 2;
    int g = lane >> 2, tg = lane & 3;

    int a_row_off = lane & 15;
    int a_col_off = (lane >> 4) << 3;
    uint32_t ahi_base = smem_u32e(&A_hi[(wm * 32 + a_row_off) * EPA + a_col_off]);
    uint32_t alo_base = smem_u32e(&A_lo[(wm * 32 + a_row_off) * EPA + a_col_off]);
    int b_lane = lane & 15;
    int b_row_off = (b_lane < 8) ? b_lane : (b_lane - 8);
    int b_col_off = (b_lane < 8) ? 0 : 8;
    uint32_t bhi_base = smem_u32e(&B_hi[(wn * 32 + b_row_off) * EPA + b_col_off]);
    uint32_t blo_base = smem_u32e(&B_lo[(wn * 32 + b_row_off) * EPA + b_col_off]);

    // ---- prefetch first tile into registers
    int tile = blockIdx.x;
    float4 pf[8];
    int pu = 0;
    {
        const float4* src = (const float4*)efeats + ((size_t)tile * 128 + row) * 16 + half * 8;
#pragma unroll
        for (int i = 0; i < 8; i++) pf[i] = ldg_cs4(src + i);
        if (t < 128) pu = u[tile * 128 + t];
    }

    while (tile < NTILES) {
        __syncthreads();   // prev mainloop done reading A; B fill visible (iter 0)

        // ---- convert prefetched regs -> A smem; publish u
        {
            unsigned* dh = (unsigned*)&A_hi[row * EPA + half * 32];
            unsigned* dl = (unsigned*)&A_lo[row * EPA + half * 32];
#pragma unroll
            for (int i = 0; i < 8; i++) {
                unsigned h0, l0, h1, l1;
                split2(pf[i].x, pf[i].y, h0, l0);
                split2(pf[i].z, pf[i].w, h1, l1);
                dh[i * 2 + 0] = h0; dh[i * 2 + 1] = h1;
                dl[i * 2 + 0] = l0; dl[i * 2 + 1] = l1;
            }
            if (t < 128) u_s[t] = pu;
        }
        __syncthreads();   // A tile + u_s ready

        size_t eb = (size_t)tile * 128;
        int ntile = tile + EGRID;

        // ---- prefetch next tile (LDG latency hides under mainloop+epilogue)
        if (ntile < NTILES) {
            const float4* src = (const float4*)efeats + ((size_t)ntile * 128 + row) * 16 + half * 8;
#pragma unroll
            for (int i = 0; i < 8; i++) pf[i] = ldg_cs4(src + i);
            if (t < 128) pu = u[ntile * 128 + t];
        }

        // ---- mainloop
        float c[2][4][4] = {};
#pragma unroll
        for (int ks = 0; ks < 4; ks++) {
            uint32_t kb = ks * 32;
            unsigned ah[2][4], al[2][4];
            ldsm_x4(ah[0], ahi_base + kb);
            ldsm_x4(ah[1], ahi_base + kb + 16 * EPA * 2);
            ldsm_x4(al[0], alo_base + kb);
            ldsm_x4(al[1], alo_base + kb + 16 * EPA * 2);
            unsigned bh[4][2], bl[4][2];
#pragma unroll
            for (int nt = 0; nt < 4; nt++) {
                ldsm_x2(bh[nt], bhi_base + kb + nt * 8 * EPA * 2);
                ldsm_x2(bl[nt], blo_base + kb + nt * 8 * EPA * 2);
            }
#pragma unroll
            for (int mt = 0; mt < 2; mt++)
#pragma unroll
                for (int nt = 0; nt < 4; nt++) {
                    mma_bf16(c[mt][nt], ah[mt], bh[nt]);
                    mma_bf16(c[mt][nt], ah[mt], bl[nt]);
                    mma_bf16(c[mt][nt], al[mt], bh[nt]);
                }
        }

        // ---- epilogue: batch gathers (MLP 16), then add + store
        float2 gv[2][4][2];
#pragma unroll
        for (int mt = 0; mt < 2; mt++) {
            int r0 = wm * 32 + mt * 16 + g;
            int u0 = u_s[r0], u1 = u_s[r0 + 8];
#pragma unroll
            for (int nt = 0; nt < 4; nt++) {
                int col = wn * 32 + nt * 8 + 2 * tg;
                gv[mt][nt][0] = *(const float2*)&g_hweb[(size_t)u0 * 64 + col];
                gv[mt][nt][1] = *(const float2*)&g_hweb[(size_t)u1 * 64 + col];
            }
        }
#pragma unroll
        for (int mt = 0; mt < 2; mt++) {
            int r0 = wm * 32 + mt * 16 + g;
            size_t e0 = eb + r0, e1 = eb + r0 + 8;
#pragma unroll
            for (int nt = 0; nt < 4; nt++) {
                int col = wn * 32 + nt * 8 + 2 * tg;
                stg_cs2(&edge_out[e0 * 64 + col],
                        c[mt][nt][0] + gv[mt][nt][0].x, c[mt][nt][1] + gv[mt][nt][0].y);
                stg_cs2(&edge_out[e1 * 64 + col],
                        c[mt][nt][2] + gv[mt][nt][1].x, c[mt][nt][3] + gv[mt][nt][1].y);
            }
        }

        tile = ntile;
    }
}

// ---------------------------------------------------------------------------
extern "C" void kernel_launch(void* const* d_in, const int* in_sizes, int n_in,
                              void* d_out, int out_size) {
    // inputs: [0]=nfeats (unused), [1]=efeats, [2]=u, [3]=v, [4]=Wn, [5]=bn, [6]=We, [7]=be
    const float* efeats = (const float*)d_in[1];
    const int*   u      = (const int*)d_in[2];
    const int*   v      = (const int*)d_in[3];
    const float* Wn     = (const float*)d_in[4];
    const float* bn     = (const float*)d_in[5];
    const float* We     = (const float*)d_in[6];
    const float* be     = (const float*)d_in[7];

    float* out      = (float*)d_out;
    float* h_out    = out;                               // [N,64]
    float* edge_out = out + (size_t)N_NODES * 64;        // [E,64]

    void* accp = nullptr; cudaGetSymbolAddress(&accp, g_acc);
    void* degp = nullptr; cudaGetSymbolAddress(&degp, g_deg);
    cudaMemsetAsync(accp, 0, sizeof(float) * 2 * N_NODES * D, 0);
    cudaMemsetAsync(degp, 0, sizeof(float) * 2 * N_NODES, 0);

    scatter_kernel<<<(E_EDGES * 16) / 256, 256>>>((const float4*)efeats, u, v);

    cudaFuncSetAttribute(node_kernel, cudaFuncAttributeMaxDynamicSharedMemorySize, N_SMEM_BYTES);
    node_kernel<<<(N_NODES + 127) / 128, 256, N_SMEM_BYTES>>>(Wn, bn, We, be, h_out);

    cudaFuncSetAttribute(edge_kernel, cudaFuncAttributeMaxDynamicSharedMemorySize, SM_EDGE_BYTES);
    edge_kernel<<<EGRID, 256, SM_EDGE_BYTES>>>(efeats, u, We, edge_out);
}

// round 16
// speedup vs baseline: 1.0981x; 1.0623x over previous
#include <cuda_runtime.h>
#include <cuda_bf16.h>
#include <cuda_fp16.h>
#include <cstdint>

#define N_NODES 100000
#define E_EDGES 1600000
#define D 64
#define EPA 72       // 16-bit row pitch for K=64 tiles (144 B)
#define EPN 136      // bf16 row pitch for K=128 tiles (272 B)
#define NTILES (E_EDGES / 128)   // 12500
#define EGRID 296                // persistent edge CTAs (2 per SM)

// Scratch (device globals — no dynamic allocation allowed)
__device__ float g_acc[2 * N_NODES * D];   // [v-sums | u-sums]
__device__ float g_deg[2 * N_NODES];       // [deg_v | deg_u]
__device__ float g_hweb[N_NODES * D];      // h @ We_h^T + be

extern __shared__ char smem_raw[];

// ---------------------------------------------------------------------------
// shared helpers
// ---------------------------------------------------------------------------
__device__ __forceinline__ void mma_bf16(float c[4], const unsigned a[4], const unsigned b[2]) {
    asm volatile(
        "mma.sync.aligned.m16n8k16.row.col.f32.bf16.bf16.f32 "
        "{%0,%1,%2,%3}, {%4,%5,%6,%7}, {%8,%9}, {%0,%1,%2,%3};"
        : "+f"(c[0]), "+f"(c[1]), "+f"(c[2]), "+f"(c[3])
        : "r"(a[0]), "r"(a[1]), "r"(a[2]), "r"(a[3]), "r"(b[0]), "r"(b[1]));
}
__device__ __forceinline__ void mma_f16(float c[4], const unsigned a[4], const unsigned b[2]) {
    asm volatile(
        "mma.sync.aligned.m16n8k16.row.col.f32.f16.f16.f32 "
        "{%0,%1,%2,%3}, {%4,%5,%6,%7}, {%8,%9}, {%0,%1,%2,%3};"
        : "+f"(c[0]), "+f"(c[1]), "+f"(c[2]), "+f"(c[3])
        : "r"(a[0]), "r"(a[1]), "r"(a[2]), "r"(a[3]), "r"(b[0]), "r"(b[1]));
}
__device__ __forceinline__ void ldsm_x4(unsigned r[4], uint32_t addr) {
    asm volatile("ldmatrix.sync.aligned.m8n8.x4.shared.b16 {%0,%1,%2,%3}, [%4];"
                 : "=r"(r[0]), "=r"(r[1]), "=r"(r[2]), "=r"(r[3]) : "r"(addr));
}
__device__ __forceinline__ void ldsm_x2(unsigned r[2], uint32_t addr) {
    asm volatile("ldmatrix.sync.aligned.m8n8.x2.shared.b16 {%0,%1}, [%2];"
                 : "=r"(r[0]), "=r"(r[1]) : "r"(addr));
}
// Fast truncation bf16 split (node kernel): hi via PRMT, lo = rn(x - hi)
__device__ __forceinline__ void split2(float x, float y, unsigned& hi, unsigned& lo) {
    unsigned xi = __float_as_uint(x), yi = __float_as_uint(y);
    asm("prmt.b32 %0, %1, %2, 0x7632;" : "=r"(hi) : "r"(xi), "r"(yi));
    float xh = __uint_as_float(xi & 0xFFFF0000u);
    float yh = __uint_as_float(yi & 0xFFFF0000u);
    float xl = x - xh, yl = y - yh;
    asm("cvt.rn.satfinite.bf16x2.f32 %0, %1, %2;" : "=r"(lo) : "f"(yl), "f"(xl));
}
// fp16 pair pack: x -> low half, y -> high half
__device__ __forceinline__ unsigned pack_f16(float x, float y) {
    unsigned r;
    asm("cvt.rn.f16x2.f32 %0, %1, %2;" : "=r"(r) : "f"(y), "f"(x));
    return r;
}
static __device__ __forceinline__ uint32_t smem_u32e(const void* p) {
    uint32_t a;
    asm("{ .reg .u64 t; cvta.to.shared.u64 t, %1; cvt.u32.u64 %0, t; }" : "=r"(a) : "l"(p));
    return a;
}
__device__ __forceinline__ float4 ldg_cs4(const float4* p) { return __ldcs(p); }
__device__ __forceinline__ void stg_cs2(float* p, float x, float y) {
    __stcs((float2*)p, make_float2(x, y));
}

// ---------------------------------------------------------------------------
// Stage 1: scatter-add (L2-atomic-bound at its floor — frozen)
// ---------------------------------------------------------------------------
__device__ __forceinline__ void red_add_v4(float* p, float4 f) {
    asm volatile("red.global.add.v4.f32 [%0], {%1,%2,%3,%4};"
                 :: "l"(p), "f"(f.x), "f"(f.y), "f"(f.z), "f"(f.w) : "memory");
}

__global__ void scatter_kernel(const float4* __restrict__ ef4,
                               const int* __restrict__ u,
                               const int* __restrict__ v) {
    int idx = blockIdx.x * blockDim.x + threadIdx.x;  // exactly E*16
    int e = idx >> 4;
    int c = idx & 15;
    float4 f = ldg_cs4(ef4 + idx);
    int vv = v[e];
    int uu = u[e];
    red_add_v4(&g_acc[(vv << 6) + (c << 2)], f);
    red_add_v4(&g_acc[(N_NODES << 6) + (uu << 6) + (c << 2)], f);
    if (c == 0) {
        atomicAdd(&g_deg[vv], 1.0f);
        atomicAdd(&g_deg[N_NODES + uu], 1.0f);
    }
}

// ---------------------------------------------------------------------------
// Stage 2 (mma, bf16x3 — h is directly checked, keep accurate)
// ---------------------------------------------------------------------------
#define N_A1HI 0
#define N_A1LO (128 * EPN)
#define N_B1HI (2 * 128 * EPN)
#define N_B1LO (2 * 128 * EPN + 64 * EPN)
#define N_ELEMS (2 * 128 * EPN + 2 * 64 * EPN)
#define N_SMEM_BYTES (N_ELEMS * 2)          // 104448
#define N_A2HI 0
#define N_A2LO (128 * EPA)
#define N_B2HI (2 * 128 * EPA)
#define N_B2LO (2 * 128 * EPA + 64 * EPA)

__global__ void __launch_bounds__(256, 2)
node_kernel(const float* __restrict__ Wn,
            const float* __restrict__ bn,
            const float* __restrict__ We,
            const float* __restrict__ be,
            float* __restrict__ h_out) {
    __nv_bfloat16* bs = (__nv_bfloat16*)smem_raw;
    int t = threadIdx.x;
    int nb = blockIdx.x * 128;

    {
        int row = t >> 1, half = t & 1;
        int n = nb + row;
        bool ok = (n < N_NODES);
        float s = 0.f;
        const float4* src = (const float4*)g_acc;
        if (half == 0) { if (ok) s = 1.0f / fmaxf(g_deg[n], 1.0f); src += (size_t)n * 16; }
        else           { if (ok) s = 1.0f / fmaxf(g_deg[N_NODES + n], 1.0f); src += (size_t)(N_NODES + n) * 16; }
        unsigned* dh = (unsigned*)&bs[N_A1HI + row * EPN + half * 64];
        unsigned* dl = (unsigned*)&bs[N_A1LO + row * EPN + half * 64];
#pragma unroll
        for (int i = 0; i < 16; i++) {
            float4 f = ok ? src[i] : make_float4(0.f, 0.f, 0.f, 0.f);
            f.x *= s; f.y *= s; f.z *= s; f.w *= s;
            unsigned h0, l0, h1, l1;
            split2(f.x, f.y, h0, l0);
            split2(f.z, f.w, h1, l1);
            dh[i * 2 + 0] = h0; dh[i * 2 + 1] = h1;
            dl[i * 2 + 0] = l0; dl[i * 2 + 1] = l1;
        }
    }
    {
        int o = t >> 2, q = t & 3;
        const float4* src = (const float4*)Wn + o * 32 + q * 8;
        unsigned* dh = (unsigned*)&bs[N_B1HI + o * EPN + q * 32];
        unsigned* dl = (unsigned*)&bs[N_B1LO + o * EPN + q * 32];
#pragma unroll
        for (int i = 0; i < 8; i++) {
            float4 f = src[i];
            unsigned h0, l0, h1, l1;
            split2(f.x, f.y, h0, l0);
            split2(f.z, f.w, h1, l1);
            dh[i * 2 + 0] = h0; dh[i * 2 + 1] = h1;
            dl[i * 2 + 0] = l0; dl[i * 2 + 1] = l1;
        }
    }
    __syncthreads();

    int wid = t >> 5, lane = t & 31;
    int wm = wid & 3, wn = wid >> 2;
    int g = lane >> 2, tg = lane & 3;

    int a_row_off = lane & 15;
    int a_col_off = (lane >> 4) << 3;
    int b_lane = lane & 15;
    int b_row_off = (b_lane < 8) ? b_lane : (b_lane - 8);
    int b_col_off = (b_lane < 8) ? 0 : 8;

    float c[2][4][4] = {};
    {
        uint32_t ahi = smem_u32e(&bs[N_A1HI + (wm * 32 + a_row_off) * EPN + a_col_off]);
        uint32_t alo = smem_u32e(&bs[N_A1LO + (wm * 32 + a_row_off) * EPN + a_col_off]);
        uint32_t bhi = smem_u32e(&bs[N_B1HI + (wn * 32 + b_row_off) * EPN + b_col_off]);
        uint32_t blo = smem_u32e(&bs[N_B1LO + (wn * 32 + b_row_off) * EPN + b_col_off]);
#pragma unroll
        for (int ks = 0; ks < 8; ks++) {
            uint32_t kb = ks * 32;
            unsigned ah[2][4], al[2][4];
            ldsm_x4(ah[0], ahi + kb);
            ldsm_x4(ah[1], ahi + kb + 16 * EPN * 2);
            ldsm_x4(al[0], alo + kb);
            ldsm_x4(al[1], alo + kb + 16 * EPN * 2);
            unsigned bh[4][2], bl[4][2];
#pragma unroll
            for (int nt = 0; nt < 4; nt++) {
                ldsm_x2(bh[nt], bhi + kb + nt * 8 * EPN * 2);
                ldsm_x2(bl[nt], blo + kb + nt * 8 * EPN * 2);
            }
#pragma unroll
            for (int mt = 0; mt < 2; mt++)
#pragma unroll
                for (int nt = 0; nt < 4; nt++) {
                    mma_bf16(c[mt][nt], ah[mt], bh[nt]);
                    mma_bf16(c[mt][nt], ah[mt], bl[nt]);
                    mma_bf16(c[mt][nt], al[mt], bh[nt]);
                }
        }
    }
    __syncthreads();

    // epilogue1: relu(+bn), write h (streaming), store A2 split of h
#pragma unroll
    for (int mt = 0; mt < 2; mt++) {
        int r0 = wm * 32 + mt * 16 + g;
        int r1 = r0 + 8;
#pragma unroll
        for (int nt = 0; nt < 4; nt++) {
            int col = wn * 32 + nt * 8 + 2 * tg;
            float2 bnv = *(const float2*)&bn[col];
            float v00 = fmaxf(c[mt][nt][0] + bnv.x, 0.f);
            float v01 = fmaxf(c[mt][nt][1] + bnv.y, 0.f);
            float v10 = fmaxf(c[mt][nt][2] + bnv.x, 0.f);
            float v11 = fmaxf(c[mt][nt][3] + bnv.y, 0.f);
            unsigned h0, l0, h1, l1;
            split2(v00, v01, h0, l0);
            split2(v10, v11, h1, l1);
            *(unsigned*)&bs[N_A2HI + r0 * EPA + col] = h0;
            *(unsigned*)&bs[N_A2LO + r0 * EPA + col] = l0;
            *(unsigned*)&bs[N_A2HI + r1 * EPA + col] = h1;
            *(unsigned*)&bs[N_A2LO + r1 * EPA + col] = l1;
            if (nb + r0 < N_NODES)
                stg_cs2(&h_out[(size_t)(nb + r0) * 64 + col], v00, v01);
            if (nb + r1 < N_NODES)
                stg_cs2(&h_out[(size_t)(nb + r1) * 64 + col], v10, v11);
        }
    }
    {
        int o = t >> 2, q = t & 3;
        const float4* src = (const float4*)We + o * 32 + q * 4;
        unsigned* dh = (unsigned*)&bs[N_B2HI + o * EPA + q * 16];
        unsigned* dl = (unsigned*)&bs[N_B2LO + o * EPA + q * 16];
#pragma unroll
        for (int i = 0; i < 4; i++) {
            float4 f = src[i];
            unsigned h0, l0, h1, l1;
            split2(f.x, f.y, h0, l0);
            split2(f.z, f.w, h1, l1);
            dh[i * 2 + 0] = h0; dh[i * 2 + 1] = h1;
            dl[i * 2 + 0] = l0; dl[i * 2 + 1] = l1;
        }
    }
    __syncthreads();

    float c2[2][4][4] = {};
    {
        uint32_t ahi = smem_u32e(&bs[N_A2HI + (wm * 32 + a_row_off) * EPA + a_col_off]);
        uint32_t alo = smem_u32e(&bs[N_A2LO + (wm * 32 + a_row_off) * EPA + a_col_off]);
        uint32_t bhi = smem_u32e(&bs[N_B2HI + (wn * 32 + b_row_off) * EPA + b_col_off]);
        uint32_t blo = smem_u32e(&bs[N_B2LO + (wn * 32 + b_row_off) * EPA + b_col_off]);
#pragma unroll
        for (int ks = 0; ks < 4; ks++) {
            uint32_t kb = ks * 32;
            unsigned ah[2][4], al[2][4];
            ldsm_x4(ah[0], ahi + kb);
            ldsm_x4(ah[1], ahi + kb + 16 * EPA * 2);
            ldsm_x4(al[0], alo + kb);
            ldsm_x4(al[1], alo + kb + 16 * EPA * 2);
            unsigned bh[4][2], bl[4][2];
#pragma unroll
            for (int nt = 0; nt < 4; nt++) {
                ldsm_x2(bh[nt], bhi + kb + nt * 8 * EPA * 2);
                ldsm_x2(bl[nt], blo + kb + nt * 8 * EPA * 2);
            }
#pragma unroll
            for (int mt = 0; mt < 2; mt++)
#pragma unroll
                for (int nt = 0; nt < 4; nt++) {
                    mma_bf16(c2[mt][nt], ah[mt], bh[nt]);
                    mma_bf16(c2[mt][nt], ah[mt], bl[nt]);
                    mma_bf16(c2[mt][nt], al[mt], bh[nt]);
                }
        }
    }

#pragma unroll
    for (int mt = 0; mt < 2; mt++) {
        int r0 = wm * 32 + mt * 16 + g;
        int r1 = r0 + 8;
#pragma unroll
        for (int nt = 0; nt < 4; nt++) {
            int col = wn * 32 + nt * 8 + 2 * tg;
            float2 bev = *(const float2*)&be[col];
            if (nb + r0 < N_NODES)
                *(float2*)&g_hweb[(size_t)(nb + r0) * 64 + col] =
                    make_float2(c2[mt][nt][0] + bev.x, c2[mt][nt][1] + bev.y);
            if (nb + r1 < N_NODES)
                *(float2*)&g_hweb[(size_t)(nb + r1) * 64 + col] =
                    make_float2(c2[mt][nt][2] + bev.x, c2[mt][nt][3] + bev.y);
        }
    }
}

// ---------------------------------------------------------------------------
// Stage 3: edge = hweb[u[e]] + efeats[e] @ We_e^T
// SINGLE-PASS fp16 mma (fp32 accum). Persistent CTAs, register prefetch,
// 2 syncs/tile — structure identical to R15, only dtype/pass-count changed.
// ---------------------------------------------------------------------------
#define S3_A 0                          // [128][EPA] f16
#define S3_B (128 * EPA)                // [64][EPA] f16
#define S3_U (128 * EPA + 64 * EPA)     // elem offset; int[128] after
#define S3_EDGE_BYTES (S3_U * 2 + 128 * 4)   // 28160

__global__ void __launch_bounds__(256, 2)
edge_kernel(const float* __restrict__ efeats,
            const int* __restrict__ u,
            const float* __restrict__ We,
            float* __restrict__ edge_out) {
    __half* hs = (__half*)smem_raw;
    __half* A_s = hs + S3_A;
    __half* B_s = hs + S3_B;
    int* u_s = (int*)(hs + S3_U);

    int t = threadIdx.x;
    int row = t >> 1, half = t & 1;

    // ---- B fill ONCE per CTA: We_e = We[:, 64:128] -> f16
    {
        int o = t >> 2, q = t & 3;
        const float4* src = (const float4*)We + o * 32 + 16 + q * 4;
        unsigned* dh = (unsigned*)&B_s[o * EPA + q * 16];
#pragma unroll
        for (int i = 0; i < 4; i++) {
            float4 f = src[i];
            dh[i * 2 + 0] = pack_f16(f.x, f.y);
            dh[i * 2 + 1] = pack_f16(f.z, f.w);
        }
    }

    int wid = t >> 5, lane = t & 31;
    int wm = wid & 3, wn = wid >> 2;
    int g = lane >> 2, tg = lane & 3;

    int a_row_off = lane & 15;
    int a_col_off = (lane >> 4) << 3;
    uint32_t a_base = smem_u32e(&A_s[(wm * 32 + a_row_off) * EPA + a_col_off]);
    int b_lane = lane & 15;
    int b_row_off = (b_lane < 8) ? b_lane : (b_lane - 8);
    int b_col_off = (b_lane < 8) ? 0 : 8;
    uint32_t b_base = smem_u32e(&B_s[(wn * 32 + b_row_off) * EPA + b_col_off]);

    // ---- prefetch first tile into registers
    int tile = blockIdx.x;
    float4 pf[8];
    int pu = 0;
    {
        const float4* src = (const float4*)efeats + ((size_t)tile * 128 + row) * 16 + half * 8;
#pragma unroll
        for (int i = 0; i < 8; i++) pf[i] = ldg_cs4(src + i);
        if (t < 128) pu = u[tile * 128 + t];
    }

    while (tile < NTILES) {
        __syncthreads();   // prev mainloop done reading A; B fill visible (iter 0)

        // ---- convert prefetched regs -> A smem (f16); publish u
        {
            unsigned* dh = (unsigned*)&A_s[row * EPA + half * 32];
#pragma unroll
            for (int i = 0; i < 8; i++) {
                dh[i * 2 + 0] = pack_f16(pf[i].x, pf[i].y);
                dh[i * 2 + 1] = pack_f16(pf[i].z, pf[i].w);
            }
            if (t < 128) u_s[t] = pu;
        }
        __syncthreads();   // A tile + u_s ready

        size_t eb = (size_t)tile * 128;
        int ntile = tile + EGRID;

        // ---- prefetch next tile (LDG latency hides under mainloop+epilogue)
        if (ntile < NTILES) {
            const float4* src = (const float4*)efeats + ((size_t)ntile * 128 + row) * 16 + half * 8;
#pragma unroll
            for (int i = 0; i < 8; i++) pf[i] = ldg_cs4(src + i);
            if (t < 128) pu = u[ntile * 128 + t];
        }

        // ---- mainloop: single fp16 pass
        float c[2][4][4] = {};
#pragma unroll
        for (int ks = 0; ks < 4; ks++) {
            uint32_t kb = ks * 32;
            unsigned ah[2][4];
            ldsm_x4(ah[0], a_base + kb);
            ldsm_x4(ah[1], a_base + kb + 16 * EPA * 2);
            unsigned bh[4][2];
#pragma unroll
            for (int nt = 0; nt < 4; nt++)
                ldsm_x2(bh[nt], b_base + kb + nt * 8 * EPA * 2);
#pragma unroll
            for (int mt = 0; mt < 2; mt++)
#pragma unroll
                for (int nt = 0; nt < 4; nt++)
                    mma_f16(c[mt][nt], ah[mt], bh[nt]);
        }

        // ---- epilogue: batch gathers (MLP 16), then add + store
        float2 gv[2][4][2];
#pragma unroll
        for (int mt = 0; mt < 2; mt++) {
            int r0 = wm * 32 + mt * 16 + g;
            int u0 = u_s[r0], u1 = u_s[r0 + 8];
#pragma unroll
            for (int nt = 0; nt < 4; nt++) {
                int col = wn * 32 + nt * 8 + 2 * tg;
                gv[mt][nt][0] = *(const float2*)&g_hweb[(size_t)u0 * 64 + col];
                gv[mt][nt][1] = *(const float2*)&g_hweb[(size_t)u1 * 64 + col];
            }
        }
#pragma unroll
        for (int mt = 0; mt < 2; mt++) {
            int r0 = wm * 32 + mt * 16 + g;
            size_t e0 = eb + r0, e1 = eb + r0 + 8;
#pragma unroll
            for (int nt = 0; nt < 4; nt++) {
                int col = wn * 32 + nt * 8 + 2 * tg;
                stg_cs2(&edge_out[e0 * 64 + col],
                        c[mt][nt][0] + gv[mt][nt][0].x, c[mt][nt][1] + gv[mt][nt][0].y);
                stg_cs2(&edge_out[e1 * 64 + col],
                        c[mt][nt][2] + gv[mt][nt][1].x, c[mt][nt][3] + gv[mt][nt][1].y);
            }
        }

        tile = ntile;
    }
}

// ---------------------------------------------------------------------------
extern "C" void kernel_launch(void* const* d_in, const int* in_sizes, int n_in,
                              void* d_out, int out_size) {
    // inputs: [0]=nfeats (unused), [1]=efeats, [2]=u, [3]=v, [4]=Wn, [5]=bn, [6]=We, [7]=be
    const float* efeats = (const float*)d_in[1];
    const int*   u      = (const int*)d_in[2];
    const int*   v      = (const int*)d_in[3];
    const float* Wn     = (const float*)d_in[4];
    const float* bn     = (const float*)d_in[5];
    const float* We     = (const float*)d_in[6];
    const float* be     = (const float*)d_in[7];

    float* out      = (float*)d_out;
    float* h_out    = out;                               // [N,64]
    float* edge_out = out + (size_t)N_NODES * 64;        // [E,64]

    void* accp = nullptr; cudaGetSymbolAddress(&accp, g_acc);
    void* degp = nullptr; cudaGetSymbolAddress(&degp, g_deg);
    cudaMemsetAsync(accp, 0, sizeof(float) * 2 * N_NODES * D, 0);
    cudaMemsetAsync(degp, 0, sizeof(float) * 2 * N_NODES, 0);

    scatter_kernel<<<(E_EDGES * 16) / 256, 256>>>((const float4*)efeats, u, v);

    cudaFuncSetAttribute(node_kernel, cudaFuncAttributeMaxDynamicSharedMemorySize, N_SMEM_BYTES);
    node_kernel<<<(N_NODES + 127) / 128, 256, N_SMEM_BYTES>>>(Wn, bn, We, be, h_out);

    cudaFuncSetAttribute(edge_kernel, cudaFuncAttributeMaxDynamicSharedMemorySize, S3_EDGE_BYTES);
    edge_kernel<<<EGRID, 256, S3_EDGE_BYTES>>>(efeats, u, We, edge_out);
}